// round 13
// baseline (speedup 1.0000x reference)
#include <cuda_runtime.h>

#define TSTEPS   2048
#define NB       512              // 4-timestep blocks
#define NREACH   16383
#define RDEPTH   8                // ring depth in blocks
#define SENT     0xFFFFFFFFu
#define DT_SUB_F 21600.0f
#define EPS_F    1e-6f

// Ring: 32 subtree roots (level 8) -> top CTA (level 9). One uint4 per block.
__device__ uint4 g_ring[32][RDEPTH];

static __device__ __forceinline__ uint4 ld_rlx4(const uint4* p) {
    uint4 v;
    asm volatile("ld.relaxed.gpu.global.v4.b32 {%0,%1,%2,%3}, [%4];"
                 : "=r"(v.x), "=r"(v.y), "=r"(v.z), "=r"(v.w) : "l"(p) : "memory");
    return v;
}
static __device__ __forceinline__ void st_rlx4(uint4* p, uint4 v) {
    asm volatile("st.relaxed.gpu.global.v4.b32 [%0], {%1,%2,%3,%4};"
                 :: "l"(p), "r"(v.x), "r"(v.y), "r"(v.z), "r"(v.w) : "memory");
}
static __device__ __forceinline__ bool any_sent(uint4 v) {
    return (v.x == SENT) | (v.y == SENT) | (v.z == SENT) | (v.w == SENT);
}
static __device__ __forceinline__ bool all_sent(uint4 v) {
    return (v.x == SENT) & (v.y == SENT) & (v.z == SENT) & (v.w == SENT);
}
static __device__ __forceinline__ uint4 wait_data4(const uint4* p, uint4 v) {
    int tries = 0;
    while (any_sent(v)) {
        v = ld_rlx4(p);
        if (++tries > 8192) __nanosleep(64);
    }
    return v;
}
static __device__ __forceinline__ void wait_free4(uint4* p, uint4 v) {
    int tries = 0;
    while (!all_sent(v)) {
        v = ld_rlx4(p);
        if (++tries > 8192) __nanosleep(64);
    }
}

static __device__ __forceinline__ float ex2f_(float x){ float y; asm("ex2.approx.f32 %0, %1;" : "=f"(y) : "f"(x)); return y; }
static __device__ __forceinline__ float lg2f_(float x){ float y; asm("lg2.approx.f32 %0, %1;" : "=f"(y) : "f"(x)); return y; }
static __device__ __forceinline__ float rcpf_(float x){ float y; asm("rcp.approx.f32 %0, %1;" : "=f"(y) : "f"(x)); return y; }

__global__ void init_ring() {
    int i = blockIdx.x * blockDim.x + threadIdx.x;
    if (i < 32 * RDEPTH * 4) ((unsigned*)g_ring)[i] = SENT;
}

__global__ void __launch_bounds__(512, 1) route_kernel(
    const float* __restrict__ lat,
    const float* __restrict__ logn,
    const float* __restrict__ lens,
    const float* __restrict__ slp,
    const float* __restrict__ wcs,
    const float* __restrict__ wes,
    const float* __restrict__ dcs,
    const float* __restrict__ des,
    float* __restrict__ out)
{
    __shared__ float sq[2][4][512];     // [phase][k within block][thread]

    const int b   = blockIdx.x;
    const int tid = threadIdx.x;
    const bool top = (b == 32);

    // ---- decode (level, element) ----
    int  j = 0, r = 0, skew = 0, cbase = 0;
    bool active = false, has_par = false, is_root = false, is_outlet = false, is_l9 = false;

    if (!top) {
        if (tid != 511) {
            const int u = 511 - tid;              // 1..511
            const int l = __clz(u) - 23;          // level 0..8 within subtree
            j = tid - (512 - (512 >> l));
            r = (16384 - (16384 >> l)) + b * (256 >> l) + j;
            skew    = l;                          // in BLOCK units
            active  = true;
            has_par = (l > 0);
            cbase   = (l > 0) ? (512 - (512 >> (l - 1))) : 0;
            is_root = (tid == 510);               // global level-8 root of subtree
        }
    } else {
        if (tid < 31) {
            const int u  = 31 - tid;              // 1..31
            const int ll = __clz(u) - 27;         // 0..4 -> global level 9..13
            j = tid - (32 - (32 >> ll));
            const int lg = 9 + ll;
            r = (16384 - (16384 >> lg)) + j;
            skew    = ll;
            active  = true;
            has_par = (ll > 0);
            cbase   = (ll > 0) ? (32 - (32 >> (ll - 1))) : 0;
            is_l9   = (ll == 0);
            is_outlet = (ll == 4);
        }
    }

    // ---- per-reach constants ----
    float negCE = 0.f, kd = 0.f, xc = 0.f, xd = 0.f;
    const float* latp = lat;
    float Q = 0.f, Ip = 0.f;
    float lbuf[4] = {0.f, 0.f, 0.f, 0.f};

    if (active) {
        const float n_man = expf(logn[r]);
        const float dx = lens[r], S = slp[r];
        const float wc = wcs[r], we = wes[r], dc = dcs[r], de = des[r];
        const float cE   = (2.0f / 3.0f) * de;
        const float l2cB = log2f(5.0f / 3.0f) + 0.5f * log2f(S) - log2f(n_man)
                         + (2.0f / 3.0f) * log2f(dc);
        negCE = -cE;
        kd = log2f(2.0f * dx) - l2cB;             // 2K = ex2(-cE*lq + kd)
        xc = 1.0f - cE - we;                      // e2 = Qref/(2 c W S dx)
        xd = -(log2f(2.0f * S * dx) + l2cB + log2f(wc));
        latp = lat + r;
        if (skew == 0) {                          // preload block 0
            #pragma unroll
            for (int k = 0; k < 4; ++k)
                lbuf[k] = __ldg(latp + (size_t)k * NREACH);
        }
    }

    // Consumer prefetch state (top CTA level-9 threads): block 0's ring data.
    uint4 pv0 = {SENT, SENT, SENT, SENT}, pv1 = pv0;
    if (is_l9) {
        pv0 = ld_rlx4(&g_ring[2 * j][0]);
        pv1 = ld_rlx4(&g_ring[2 * j + 1][0]);
    }
    const uint4 SENT4 = {SENT, SENT, SENT, SENT};

    const int ITER = top ? (NB + 5) : (NB + 9);

    for (int bi = 0; bi < ITER; ++bi) {
        const int tb  = bi - skew;
        const int p   = bi & 1;
        const bool run = active && (tb >= 0) && (tb < NB);

        // ---- prefetch next block's lateral inflows ----
        float ln[4] = {0.f, 0.f, 0.f, 0.f};
        {
            const int tbn = tb + 1;
            if (active && tbn >= 0 && tbn < NB) {
                const float* bp = latp + (size_t)(4 * tbn) * NREACH;
                #pragma unroll
                for (int k = 0; k < 4; ++k)
                    ln[k] = __ldg(bp + (size_t)k * NREACH);
            }
        }

        // ---- early-issue root slot-free check (one v4 load) ----
        uint4 vfree = SENT4;
        uint4* wslot = nullptr;
        if (run && is_root) {
            wslot = &g_ring[b][tb & (RDEPTH - 1)];
            vfree = ld_rlx4(wslot);
        }

        if (run) {
            // Level-9: consume both children's blocks (usually satisfied by prefetch).
            float csum[4];
            if (is_l9) {
                const int s = tb & (RDEPTH - 1);
                uint4* c0 = &g_ring[2 * j][s];
                uint4* c1 = &g_ring[2 * j + 1][s];
                const uint4 v0 = wait_data4(c0, pv0);
                const uint4 v1 = wait_data4(c1, pv1);
                st_rlx4(c0, SENT4);               // ack
                st_rlx4(c1, SENT4);
                csum[0] = __uint_as_float(v0.x) + __uint_as_float(v1.x);
                csum[1] = __uint_as_float(v0.y) + __uint_as_float(v1.y);
                csum[2] = __uint_as_float(v0.z) + __uint_as_float(v1.z);
                csum[3] = __uint_as_float(v0.w) + __uint_as_float(v1.w);
                if (tb + 1 < NB) {                // prefetch next block's payloads
                    const int s2 = (tb + 1) & (RDEPTH - 1);
                    pv0 = ld_rlx4(&g_ring[2 * j][s2]);
                    pv1 = ld_rlx4(&g_ring[2 * j + 1][s2]);
                }
            }

            float qk[4];
            #pragma unroll
            for (int k = 0; k < 4; ++k) {
                float Inew = lbuf[k];
                if (has_par)
                    Inew += sq[p ^ 1][k][cbase + 2 * j] + sq[p ^ 1][k][cbase + 2 * j + 1];
                else if (is_l9)
                    Inew += csum[k];

                // 4 Muskingum-Cunge substeps
                float q = Q, io = Ip;
                #pragma unroll
                for (int s4 = 0; s4 < 4; ++s4) {
                    const float Qref = fmaxf((Inew + io + q) * (1.0f / 3.0f), EPS_F);
                    const float lq  = lg2f_(Qref);
                    const float K2  = ex2f_(fmaf(negCE, lq, kd));    // 2K
                    const float e2  = ex2f_(fmaf(xc, lq, xd));       // Qref/(2cWSdx)
                    const float X   = fmaxf(0.5f - e2, 0.0f);
                    const float A   = K2 * X;
                    const float Bq  = K2 - A;
                    const float Dd  = Bq + DT_SUB_F;
                    const float rD  = rcpf_(Dd);
                    float acc = (DT_SUB_F - A) * Inew;
                    acc = fmaf(DT_SUB_F + A, io, acc);
                    acc = fmaf(Bq - DT_SUB_F, q, acc);
                    q  = fmaxf(acc * rD, 0.0f);
                    io = Inew;
                }
                Q = q; Ip = Inew;
                qk[k] = q;
            }

            // ---- publish ----
            if (is_root) {
                wait_free4(wslot, vfree);         // rarely spins (lead << RDEPTH)
                uint4 pay;
                pay.x = __float_as_uint(qk[0]);
                pay.y = __float_as_uint(qk[1]);
                pay.z = __float_as_uint(qk[2]);
                pay.w = __float_as_uint(qk[3]);
                st_rlx4(wslot, pay);
            } else if (is_outlet) {
                #pragma unroll
                for (int k = 0; k < 4; ++k) out[4 * tb + k] = qk[k];
            } else {
                #pragma unroll
                for (int k = 0; k < 4; ++k) sq[p][k][tid] = qk[k];
            }
        }

        #pragma unroll
        for (int k = 0; k < 4; ++k) lbuf[k] = ln[k];

        __syncthreads();
    }
}

extern "C" void kernel_launch(void* const* d_in, const int* in_sizes, int n_in,
                              void* d_out, int out_size) {
    const float* lat  = (const float*)d_in[0];
    const float* logn = (const float*)d_in[1];
    const float* lens = (const float*)d_in[2];
    const float* slp  = (const float*)d_in[3];
    const float* wcs  = (const float*)d_in[4];
    const float* wes  = (const float*)d_in[5];
    const float* dcs  = (const float*)d_in[6];
    const float* des  = (const float*)d_in[7];
    float* out = (float*)d_out;

    init_ring<<<1, 1024>>>();
    route_kernel<<<33, 512>>>(lat, logn, lens, slp, wcs, wes, dcs, des, out);
}

// round 15
// speedup vs baseline: 2.0225x; 2.0225x over previous
#include <cuda_runtime.h>

#define TSTEPS   2048
#define BLK      8                // timesteps per wavefront block
#define NB       (TSTEPS / BLK)   // 256 blocks
#define NREACH   16383
#define RDEPTH   8                // ring depth in blocks
#define SENT     0xFFFFFFFFu
#define DT_SUB_F 21600.0f
#define EPS_F    1e-6f

// Ring: 64 subtree roots (level 7) -> top CTA (level 8). Two uint4 per block.
__device__ uint4 g_ring[64][RDEPTH][2];

static __device__ __forceinline__ uint4 ld_rlx4(const uint4* p) {
    uint4 v;
    asm volatile("ld.relaxed.gpu.global.v4.b32 {%0,%1,%2,%3}, [%4];"
                 : "=r"(v.x), "=r"(v.y), "=r"(v.z), "=r"(v.w) : "l"(p) : "memory");
    return v;
}
static __device__ __forceinline__ void st_rlx4(uint4* p, uint4 v) {
    asm volatile("st.relaxed.gpu.global.v4.b32 [%0], {%1,%2,%3,%4};"
                 :: "l"(p), "r"(v.x), "r"(v.y), "r"(v.z), "r"(v.w) : "memory");
}
static __device__ __forceinline__ bool any_sent(uint4 v) {
    return (v.x == SENT) | (v.y == SENT) | (v.z == SENT) | (v.w == SENT);
}
static __device__ __forceinline__ bool all_sent(uint4 v) {
    return (v.x == SENT) & (v.y == SENT) & (v.z == SENT) & (v.w == SENT);
}
static __device__ __forceinline__ uint4 wait_data4(const uint4* p, uint4 v) {
    int tries = 0;
    while (any_sent(v)) {
        v = ld_rlx4(p);
        if (++tries > 8192) __nanosleep(64);
    }
    return v;
}
static __device__ __forceinline__ void wait_free4(uint4* p, uint4 v) {
    int tries = 0;
    while (!all_sent(v)) {
        v = ld_rlx4(p);
        if (++tries > 8192) __nanosleep(64);
    }
}

static __device__ __forceinline__ float ex2f_(float x){ float y; asm("ex2.approx.f32 %0, %1;" : "=f"(y) : "f"(x)); return y; }
static __device__ __forceinline__ float lg2f_(float x){ float y; asm("lg2.approx.f32 %0, %1;" : "=f"(y) : "f"(x)); return y; }
static __device__ __forceinline__ float rcpf_(float x){ float y; asm("rcp.approx.f32 %0, %1;" : "=f"(y) : "f"(x)); return y; }

__global__ void init_ring() {
    int i = blockIdx.x * blockDim.x + threadIdx.x;
    if (i < 64 * RDEPTH * 8) ((unsigned*)g_ring)[i] = SENT;
}

__global__ void __launch_bounds__(256, 1) route_kernel(
    const float* __restrict__ lat,
    const float* __restrict__ logn,
    const float* __restrict__ lens,
    const float* __restrict__ slp,
    const float* __restrict__ wcs,
    const float* __restrict__ wes,
    const float* __restrict__ dcs,
    const float* __restrict__ des,
    float* __restrict__ out)
{
    __shared__ float sq[2][BLK][256];   // [phase][k within block][thread]

    const int b   = blockIdx.x;
    const int tid = threadIdx.x;
    const bool top = (b == 64);

    // ---- decode (level, element) ----
    int  j = 0, r = 0, skew = 0, cbase = 0;
    bool active = false, has_par = false, is_root = false, is_outlet = false, is_l8 = false;

    if (!top) {
        if (tid != 255) {
            const int u = 255 - tid;              // 1..255
            const int l = __clz(u) - 24;          // level 0..7 within subtree
            j = tid - (256 - (256 >> l));
            r = (16384 - (16384 >> l)) + b * (128 >> l) + j;
            skew    = l;                          // in BLOCK units
            active  = true;
            has_par = (l > 0);
            cbase   = (l > 0) ? (256 - (256 >> (l - 1))) : 0;
            is_root = (tid == 254);
        }
    } else {
        if (tid < 63) {
            const int u  = 63 - tid;              // 1..63
            const int ll = __clz(u) - 26;         // 0..5 -> global level 8..13
            j = tid - (64 - (64 >> ll));
            const int lg = 8 + ll;
            r = (16384 - (16384 >> lg)) + j;
            skew    = ll;
            active  = true;
            has_par = (ll > 0);
            cbase   = (ll > 0) ? (64 - (64 >> (ll - 1))) : 0;
            is_l8   = (ll == 0);
            is_outlet = (ll == 5);
        }
    }

    // ---- per-reach constants ----
    float negCE = 0.f, kd = 0.f, xc = 0.f, xd = 0.f;
    const float* latp = lat;
    float Q = 0.f, Ip = 0.f;
    float lbuf[BLK];
    #pragma unroll
    for (int k = 0; k < BLK; ++k) lbuf[k] = 0.f;

    if (active) {
        const float n_man = expf(logn[r]);
        const float dx = lens[r], S = slp[r];
        const float wc = wcs[r], we = wes[r], dc = dcs[r], de = des[r];
        const float cE   = (2.0f / 3.0f) * de;
        const float l2cB = log2f(5.0f / 3.0f) + 0.5f * log2f(S) - log2f(n_man)
                         + (2.0f / 3.0f) * log2f(dc);
        negCE = -cE;
        kd = log2f(2.0f * dx) - l2cB;             // 2K = ex2(-cE*lq + kd)
        xc = 1.0f - cE - we;                      // e2 = Qref/(2 c W S dx)
        xd = -(log2f(2.0f * S * dx) + l2cB + log2f(wc));
        latp = lat + r;
        if (skew == 0) {                          // preload block 0
            #pragma unroll
            for (int k = 0; k < BLK; ++k)
                lbuf[k] = __ldg(latp + (size_t)k * NREACH);
        }
    }

    // Consumer prefetch state (top CTA level-8 threads): block 0's ring data.
    const uint4 SENT4 = {SENT, SENT, SENT, SENT};
    uint4 pv0a = SENT4, pv0b = SENT4, pv1a = SENT4, pv1b = SENT4;
    if (is_l8) {
        pv0a = ld_rlx4(&g_ring[2 * j][0][0]);
        pv0b = ld_rlx4(&g_ring[2 * j][0][1]);
        pv1a = ld_rlx4(&g_ring[2 * j + 1][0][0]);
        pv1b = ld_rlx4(&g_ring[2 * j + 1][0][1]);
    }

    const int ITER = NB + 8;

    for (int bi = 0; bi < ITER; ++bi) {
        const int tb  = bi - skew;
        const int p   = bi & 1;
        const bool run = active && (tb >= 0) && (tb < NB);

        // ---- prefetch next block's lateral inflows (consumed next iteration) ----
        float ln[BLK];
        #pragma unroll
        for (int k = 0; k < BLK; ++k) ln[k] = 0.f;
        {
            const int tbn = tb + 1;
            if (active && tbn >= 0 && tbn < NB) {
                const float* bp = latp + (size_t)(BLK * tbn) * NREACH;
                #pragma unroll
                for (int k = 0; k < BLK; ++k)
                    ln[k] = __ldg(bp + (size_t)k * NREACH);
            }
        }

        // ---- early-issue root slot-free check (two v4 loads) ----
        uint4 vfa = SENT4, vfb = SENT4;
        uint4* wslot = nullptr;
        if (run && is_root) {
            wslot = &g_ring[b][tb & (RDEPTH - 1)][0];
            vfa = ld_rlx4(wslot);
            vfb = ld_rlx4(wslot + 1);
        }

        if (run) {
            // Level-8: consume both children's blocks (usually satisfied by prefetch).
            float csum[BLK];
            if (is_l8) {
                const int s = tb & (RDEPTH - 1);
                uint4* c0 = &g_ring[2 * j][s][0];
                uint4* c1 = &g_ring[2 * j + 1][s][0];
                const uint4 v0a = wait_data4(c0,     pv0a);
                const uint4 v0b = wait_data4(c0 + 1, pv0b);
                const uint4 v1a = wait_data4(c1,     pv1a);
                const uint4 v1b = wait_data4(c1 + 1, pv1b);
                st_rlx4(c0,     SENT4);           // ack
                st_rlx4(c0 + 1, SENT4);
                st_rlx4(c1,     SENT4);
                st_rlx4(c1 + 1, SENT4);
                csum[0] = __uint_as_float(v0a.x) + __uint_as_float(v1a.x);
                csum[1] = __uint_as_float(v0a.y) + __uint_as_float(v1a.y);
                csum[2] = __uint_as_float(v0a.z) + __uint_as_float(v1a.z);
                csum[3] = __uint_as_float(v0a.w) + __uint_as_float(v1a.w);
                csum[4] = __uint_as_float(v0b.x) + __uint_as_float(v1b.x);
                csum[5] = __uint_as_float(v0b.y) + __uint_as_float(v1b.y);
                csum[6] = __uint_as_float(v0b.z) + __uint_as_float(v1b.z);
                csum[7] = __uint_as_float(v0b.w) + __uint_as_float(v1b.w);
                if (tb + 1 < NB) {                // prefetch next block's payloads
                    const int s2 = (tb + 1) & (RDEPTH - 1);
                    pv0a = ld_rlx4(&g_ring[2 * j][s2][0]);
                    pv0b = ld_rlx4(&g_ring[2 * j][s2][1]);
                    pv1a = ld_rlx4(&g_ring[2 * j + 1][s2][0]);
                    pv1b = ld_rlx4(&g_ring[2 * j + 1][s2][1]);
                }
            }

            float qk[BLK];
            #pragma unroll
            for (int k = 0; k < BLK; ++k) {
                float Inew = lbuf[k];
                if (has_par)
                    Inew += sq[p ^ 1][k][cbase + 2 * j] + sq[p ^ 1][k][cbase + 2 * j + 1];
                else if (is_l8)
                    Inew += csum[k];

                // 4 Muskingum-Cunge substeps
                float q = Q, io = Ip;
                #pragma unroll
                for (int s4 = 0; s4 < 4; ++s4) {
                    const float Qref = fmaxf((Inew + io + q) * (1.0f / 3.0f), EPS_F);
                    const float lq  = lg2f_(Qref);
                    const float K2  = ex2f_(fmaf(negCE, lq, kd));    // 2K
                    const float e2  = ex2f_(fmaf(xc, lq, xd));       // Qref/(2cWSdx)
                    const float X   = fmaxf(0.5f - e2, 0.0f);
                    const float A   = K2 * X;
                    const float Bq  = K2 - A;
                    const float Dd  = Bq + DT_SUB_F;
                    const float rD  = rcpf_(Dd);
                    float acc = (DT_SUB_F - A) * Inew;
                    acc = fmaf(DT_SUB_F + A, io, acc);
                    acc = fmaf(Bq - DT_SUB_F, q, acc);
                    q  = fmaxf(acc * rD, 0.0f);
                    io = Inew;
                }
                Q = q; Ip = Inew;
                qk[k] = q;
            }

            // ---- publish ----
            if (is_root) {
                wait_free4(wslot,     vfa);       // rarely spins (lead << RDEPTH)
                wait_free4(wslot + 1, vfb);
                uint4 pa, pb;
                pa.x = __float_as_uint(qk[0]); pa.y = __float_as_uint(qk[1]);
                pa.z = __float_as_uint(qk[2]); pa.w = __float_as_uint(qk[3]);
                pb.x = __float_as_uint(qk[4]); pb.y = __float_as_uint(qk[5]);
                pb.z = __float_as_uint(qk[6]); pb.w = __float_as_uint(qk[7]);
                st_rlx4(wslot,     pa);
                st_rlx4(wslot + 1, pb);
            } else if (is_outlet) {
                #pragma unroll
                for (int k = 0; k < BLK; ++k) out[BLK * tb + k] = qk[k];
            } else {
                #pragma unroll
                for (int k = 0; k < BLK; ++k) sq[p][k][tid] = qk[k];
            }
        }

        #pragma unroll
        for (int k = 0; k < BLK; ++k) lbuf[k] = ln[k];

        __syncthreads();
    }
}

extern "C" void kernel_launch(void* const* d_in, const int* in_sizes, int n_in,
                              void* d_out, int out_size) {
    const float* lat  = (const float*)d_in[0];
    const float* logn = (const float*)d_in[1];
    const float* lens = (const float*)d_in[2];
    const float* slp  = (const float*)d_in[3];
    const float* wcs  = (const float*)d_in[4];
    const float* wes  = (const float*)d_in[5];
    const float* dcs  = (const float*)d_in[6];
    const float* des  = (const float*)d_in[7];
    float* out = (float*)d_out;

    init_ring<<<(64 * RDEPTH * 8 + 255) / 256, 256>>>();
    route_kernel<<<65, 256>>>(lat, logn, lens, slp, wcs, wes, dcs, des, out);
}